// round 16
// baseline (speedup 1.0000x reference)
#include <cuda_runtime.h>
#include <cuda_fp16.h>
#include <cstdint>
#include <cstddef>

// Problem constants
#define NWIN   4096
#define TT     49
#define DIM    384
#define HEADS  12
#define HD     32
#define NQKV   1152
#define MROWS  (NWIN * TT)            // 200704
#define SCALE  0.17677669529663687f
#define EPS    1e-6f

#define AST    40                     // smem row stride in fp16 elems (80 B)
#define STAGEB (128 * AST * 2)        // 10240 bytes per stage per operand

// ---------------------------------------------------------------------------
// Scratch (device globals; no allocations allowed)
// ---------------------------------------------------------------------------
__device__ __half g_qkv16[(size_t)MROWS * NQKV]; // 462 MB fp16 intermediate
__device__ __half g_x16[(size_t)MROWS * DIM];
__device__ __half g_c16[(size_t)MROWS * DIM];
__device__ __half g_w16[NQKV * DIM];             // qkv_w rounded to fp16
__device__ __half g_p16[DIM * DIM];              // proj_w rounded to fp16
__device__ float  g_biasg[HEADS * TT * TT];

// ---------------------------------------------------------------------------
// PTX helpers
// ---------------------------------------------------------------------------
__device__ __forceinline__ uint32_t smem_u32(const void* p) {
    uint32_t a;
    asm("{ .reg .u64 t; cvta.to.shared.u64 t, %1; cvt.u32.u64 %0, t; }"
        : "=r"(a) : "l"(p));
    return a;
}
__device__ __forceinline__ void cp_async16(uint32_t dst, const void* src) {
    asm volatile("cp.async.cg.shared.global [%0], [%1], 16;"
                 :: "r"(dst), "l"(src) : "memory");
}
__device__ __forceinline__ void ldsm4(uint32_t& r0, uint32_t& r1,
                                      uint32_t& r2, uint32_t& r3, uint32_t a) {
    asm volatile("ldmatrix.sync.aligned.m8n8.x4.shared.b16 {%0,%1,%2,%3}, [%4];"
                 : "=r"(r0), "=r"(r1), "=r"(r2), "=r"(r3) : "r"(a));
}
__device__ __forceinline__ void lds32(uint32_t& r, uint32_t a) {
    asm volatile("ld.shared.b32 %0, [%1];" : "=r"(r) : "r"(a));
}
__device__ __forceinline__ void mma16816(float* d, const uint32_t* a,
                                         const uint32_t* b) {
    asm volatile(
        "mma.sync.aligned.m16n8k16.row.col.f32.f16.f16.f32 "
        "{%0,%1,%2,%3}, {%4,%5,%6,%7}, {%8,%9}, {%0,%1,%2,%3};"
        : "+f"(d[0]), "+f"(d[1]), "+f"(d[2]), "+f"(d[3])
        : "r"(a[0]), "r"(a[1]), "r"(a[2]), "r"(a[3]), "r"(b[0]), "r"(b[1]));
}

// ---------------------------------------------------------------------------
// HMMA GEMM (validated R15 kernel — unchanged)
// ---------------------------------------------------------------------------
template<bool ADD_BIAS, bool OUT_HALF>
__global__ __launch_bounds__(256, 2)
void gemm_hmma1(const __half* __restrict__ A,
                const __half* __restrict__ B,
                const float* __restrict__ bias, void* __restrict__ Cv,
                int M, int N, int K) {
    __shared__ __half As[2][128 * AST];
    __shared__ __half Bs[2][128 * AST];

    const int tid  = threadIdx.x;
    const int wid  = tid >> 5, lane = tid & 31;
    const int bm   = blockIdx.y * 128, bn = blockIdx.x * 128;
    const int wm   = (wid >> 2) * 64,  wn = (wid & 3) * 32;

    float acc[4][4][4];
#pragma unroll
    for (int i = 0; i < 4; i++)
#pragma unroll
        for (int j = 0; j < 4; j++)
#pragma unroll
            for (int r = 0; r < 4; r++) acc[i][j][r] = 0.f;

    const int nch = K >> 5;          // 12 for K=384

    const uint32_t sA = smem_u32(As);
    const uint32_t sB = smem_u32(Bs);

    const int lrow = tid >> 2;
    const int lhf  = tid & 3;

    const int m_l  = (lane & 7) + ((lane >> 3) & 1) * 8;
    const int kb_l = (lane >> 4) * 8;
    const int bn_l = lane >> 2;
    const int bk_l = (lane & 3) * 2;

#define PREFETCH(c, s)                                                         \
    do {                                                                       \
        int kc = (c) * 32;                                                     \
        _Pragma("unroll")                                                      \
        for (int j = 0; j < 2; j++) {                                          \
            int row = lrow + j * 64;                                           \
            uint32_t doff = (uint32_t)(s) * STAGEB + (row * AST + lhf * 8) * 2;\
            cp_async16(sA + doff, A + (size_t)(bm + row) * K + kc + lhf * 8);  \
            cp_async16(sB + doff, B + (size_t)(bn + row) * K + kc + lhf * 8);  \
        }                                                                      \
        asm volatile("cp.async.commit_group;" ::: "memory");                   \
    } while (0)

    PREFETCH(0, 0);

    for (int c = 0; c < nch; c++) {
        if (c + 1 < nch) {
            PREFETCH(c + 1, (c + 1) & 1);
            asm volatile("cp.async.wait_group 1;" ::: "memory");
        } else {
            asm volatile("cp.async.wait_group 0;" ::: "memory");
        }
        __syncthreads();

        const uint32_t aBase = sA + (uint32_t)(c & 1) * STAGEB;
        const uint32_t bBase = sB + (uint32_t)(c & 1) * STAGEB;
#pragma unroll
        for (int ks = 0; ks < 2; ks++) {
            const int k0 = ks * 16;
            uint32_t a[4][4], b[4][2];
#pragma unroll
            for (int mf = 0; mf < 4; mf++) {
                int m = wm + mf * 16 + m_l;
                ldsm4(a[mf][0], a[mf][1], a[mf][2], a[mf][3],
                      aBase + (m * AST + k0 + kb_l) * 2);
            }
#pragma unroll
            for (int nf = 0; nf < 4; nf++) {
                int n = wn + nf * 8 + bn_l;
                uint32_t addr = bBase + (n * AST + k0 + bk_l) * 2;
                lds32(b[nf][0], addr);
                lds32(b[nf][1], addr + 16);
            }
#pragma unroll
            for (int mf = 0; mf < 4; mf++)
#pragma unroll
                for (int nf = 0; nf < 4; nf++)
                    mma16816(acc[mf][nf], a[mf], b[nf]);
        }
        __syncthreads();
    }
#undef PREFETCH

#pragma unroll
    for (int mf = 0; mf < 4; mf++) {
        int m0 = bm + wm + mf * 16 + (lane >> 2);
#pragma unroll
        for (int nf = 0; nf < 4; nf++) {
            int n0 = bn + wn + nf * 8 + (lane & 3) * 2;
            float bx = 0.f, by = 0.f;
            if (ADD_BIAS) { bx = bias[n0]; by = bias[n0 + 1]; }
            float2 v0 = make_float2(acc[mf][nf][0] + bx, acc[mf][nf][1] + by);
            float2 v1 = make_float2(acc[mf][nf][2] + bx, acc[mf][nf][3] + by);
            if (OUT_HALF) {
                __half* C = (__half*)Cv;
                *(__half2*)&C[(size_t)m0 * N + n0] =
                    __halves2half2(__float2half_rn(v0.x), __float2half_rn(v0.y));
                *(__half2*)&C[(size_t)(m0 + 8) * N + n0] =
                    __halves2half2(__float2half_rn(v1.x), __float2half_rn(v1.y));
            } else {
                float* C = (float*)Cv;
                *(float2*)&C[(size_t)m0 * N + n0]       = v0;
                *(float2*)&C[(size_t)(m0 + 8) * N + n0] = v1;
            }
        }
    }
}

// ---------------------------------------------------------------------------
// fp32 -> fp16 round
// ---------------------------------------------------------------------------
__global__ void round_kernel(const float* __restrict__ x,
                             __half* __restrict__ y, int n4) {
    int i = blockIdx.x * blockDim.x + threadIdx.x;
    if (i < n4) {
        float4 v = ((const float4*)x)[i];
        ((__half2*)y)[2 * i]     = __halves2half2(__float2half_rn(v.x), __float2half_rn(v.y));
        ((__half2*)y)[2 * i + 1] = __halves2half2(__float2half_rn(v.z), __float2half_rn(v.w));
    }
}

// ---------------------------------------------------------------------------
// bias gather
// ---------------------------------------------------------------------------
__global__ void gather_bias_kernel(const float* __restrict__ bt,
                                   const int* __restrict__ ri,
                                   float* __restrict__ ob) {
    int idx = blockIdx.x * blockDim.x + threadIdx.x;
    if (idx < HEADS * TT * TT) {
        int h = idx / (TT * TT);
        int p = idx - h * (TT * TT);
        ob[idx] = bt[ri[p] * HEADS + h];
    }
}

// ---------------------------------------------------------------------------
// Tensor-core fused attention. Block = (window, head), 128 thr, 4 warps.
// rmsnorm folded as per-row fp32 scales (rq_i, rk_j) applied to the QK^T
// fragments; nwq*nwk folded into K once. FA2-style fragment softmax; PV HMMA.
// ---------------------------------------------------------------------------
__global__ __launch_bounds__(128)
void win_attn_mma(const __half* __restrict__ qkv,
                  const float* __restrict__ qn_w,
                  const float* __restrict__ kn_w,
                  const float* __restrict__ biasg,
                  __half* __restrict__ c16) {
    __shared__ __half Qs[64][40];     // rows 49..63 zero
    __shared__ __half Ks[56][40];     // k * (nwq*nwk); rows 49..55 zero
    __shared__ __half VT[32][72];     // V^T [d][key], keys 49..63 zero
    __shared__ float  rqs[64], rks[64];
    __shared__ float  kw[HD];

    const int b = blockIdx.x, h = blockIdx.y;
    const int tid = threadIdx.x, wid = tid >> 5, lane = tid & 31;

    // zero smem
    for (int i = tid; i < 1280; i += 128) ((uint32_t*)Qs)[i] = 0;
    for (int i = tid; i < 1120; i += 128) ((uint32_t*)Ks)[i] = 0;
    for (int i = tid; i < 1152; i += 128) ((uint32_t*)VT)[i] = 0;
    if (tid < 64) { rqs[tid] = 0.f; rks[tid] = 0.f; }
    if (tid < HD) kw[tid] = qn_w[tid] * kn_w[tid];
    __syncthreads();

    // Phase 1: per-row load + norm factors + layouts (threads 0..48)
    if (tid < TT) {
        const __half* rp = qkv + ((size_t)b * TT + tid) * NQKV + h * HD;
        // q: store raw, compute rq
        uint4 qr[4];
#pragma unroll
        for (int i = 0; i < 4; i++) qr[i] = *(const uint4*)(rp + i * 8);
        float ssq = 0.f;
#pragma unroll
        for (int i = 0; i < 4; i++) {
            __half2* hp = (__half2*)&qr[i];
#pragma unroll
            for (int j = 0; j < 4; j++) {
                float2 f = __half22float2(hp[j]);
                ssq += f.x * f.x + f.y * f.y;
            }
        }
#pragma unroll
        for (int i = 0; i < 4; i++) *(uint4*)&Qs[tid][i * 8] = qr[i];
        rqs[tid] = rsqrtf(ssq * (1.f / HD) + EPS) * SCALE;
        // k: store k*kw, compute rk from raw k
        float ssk = 0.f;
#pragma unroll
        for (int i = 0; i < 4; i++) {
            uint4 kr = *(const uint4*)(rp + DIM + i * 8);
            __half2* hp = (__half2*)&kr;
#pragma unroll
            for (int j = 0; j < 4; j++) {
                float2 f = __half22float2(hp[j]);
                ssk += f.x * f.x + f.y * f.y;
                int d = i * 8 + j * 2;
                *(__half2*)&Ks[tid][d] =
                    __floats2half2_rn(f.x * kw[d], f.y * kw[d + 1]);
            }
        }
        rks[tid] = rsqrtf(ssk * (1.f / HD) + EPS);
        // v: transpose into VT
#pragma unroll
        for (int i = 0; i < 4; i++) {
            uint4 vr = *(const uint4*)(rp + 2 * DIM + i * 8);
            __half2* hp = (__half2*)&vr;
#pragma unroll
            for (int j = 0; j < 4; j++) {
                int d = i * 8 + j * 2;
                VT[d][tid]     = __low2half(hp[j]);
                VT[d + 1][tid] = __high2half(hp[j]);
            }
        }
    }
    __syncthreads();

    // Phase 2: per-warp 16-row M-tile
    const int m_l  = (lane & 7) + ((lane >> 3) & 1) * 8;
    const int kb_l = (lane >> 4) * 8;
    const int cb   = 2 * (lane & 3);
    const int r0   = wid * 16 + (lane >> 2);
    const int r1   = r0 + 8;
    const bool r0ok = r0 < TT, r1ok = r1 < TT;

    // Q A-frags (k 0..15 and 16..31)
    uint32_t qa0[4], qa1[4];
    {
        uint32_t qaddr = smem_u32(&Qs[wid * 16 + m_l][kb_l]);
        ldsm4(qa0[0], qa0[1], qa0[2], qa0[3], qaddr);
        ldsm4(qa1[0], qa1[1], qa1[2], qa1[3], qaddr + 32);
    }

    // S = QK^T
    float sa[7][4];
#pragma unroll
    for (int nt = 0; nt < 7; nt++) {
        sa[nt][0] = sa[nt][1] = sa[nt][2] = sa[nt][3] = 0.f;
        uint32_t baddr = smem_u32(&Ks[nt * 8 + (lane >> 2)][cb]);
        uint32_t b0[2], b1[2];
        lds32(b0[0], baddr);      lds32(b0[1], baddr + 16);
        lds32(b1[0], baddr + 32); lds32(b1[1], baddr + 48);
        mma16816(sa[nt], qa0, b0);
        mma16816(sa[nt], qa1, b1);
    }

    // scale + bias + masked softmax (rows r0/r1 independent)
    const float rq0 = rqs[r0], rq1 = rqs[r1];
    const float* bb = biasg + (size_t)h * TT * TT;
    float sv[7][4];
    float m0 = -1e30f, m1 = -1e30f;
#pragma unroll
    for (int nt = 0; nt < 7; nt++) {
        int c0 = nt * 8 + cb, c1 = c0 + 1;
        float rk0 = rks[c0], rk1 = rks[c1];
        sv[nt][0] = (r0ok && c0 < TT) ? sa[nt][0] * rq0 * rk0 + __ldg(bb + r0 * TT + c0) : -1e30f;
        sv[nt][1] = (r0ok && c1 < TT) ? sa[nt][1] * rq0 * rk1 + __ldg(bb + r0 * TT + c1) : -1e30f;
        sv[nt][2] = (r1ok && c0 < TT) ? sa[nt][2] * rq1 * rk0 + __ldg(bb + r1 * TT + c0) : -1e30f;
        sv[nt][3] = (r1ok && c1 < TT) ? sa[nt][3] * rq1 * rk1 + __ldg(bb + r1 * TT + c1) : -1e30f;
        m0 = fmaxf(m0, fmaxf(sv[nt][0], sv[nt][1]));
        m1 = fmaxf(m1, fmaxf(sv[nt][2], sv[nt][3]));
    }
    m0 = fmaxf(m0, __shfl_xor_sync(0xffffffffu, m0, 1));
    m0 = fmaxf(m0, __shfl_xor_sync(0xffffffffu, m0, 2));
    m1 = fmaxf(m1, __shfl_xor_sync(0xffffffffu, m1, 1));
    m1 = fmaxf(m1, __shfl_xor_sync(0xffffffffu, m1, 2));

    float sum0 = 0.f, sum1 = 0.f;
    uint32_t ph[7][2];
#pragma unroll
    for (int nt = 0; nt < 7; nt++) {
        float p00 = __expf(sv[nt][0] - m0), p01 = __expf(sv[nt][1] - m0);
        float p10 = __expf(sv[nt][2] - m1), p11 = __expf(sv[nt][3] - m1);
        sum0 += p00 + p01;
        sum1 += p10 + p11;
        __half2 h0 = __floats2half2_rn(p00, p01);
        __half2 h1 = __floats2half2_rn(p10, p11);
        ph[nt][0] = *(uint32_t*)&h0;
        ph[nt][1] = *(uint32_t*)&h1;
    }
    sum0 += __shfl_xor_sync(0xffffffffu, sum0, 1);
    sum0 += __shfl_xor_sync(0xffffffffu, sum0, 2);
    sum1 += __shfl_xor_sync(0xffffffffu, sum1, 1);
    sum1 += __shfl_xor_sync(0xffffffffu, sum1, 2);

    // O = P @ V  (A = P frags, B = VT)
    float oa[4][4];
#pragma unroll
    for (int nd = 0; nd < 4; nd++)
        oa[nd][0] = oa[nd][1] = oa[nd][2] = oa[nd][3] = 0.f;
#pragma unroll
    for (int kt = 0; kt < 4; kt++) {
        uint32_t A[4];
        A[0] = ph[2 * kt][0];
        A[1] = ph[2 * kt][1];
        A[2] = (kt < 3) ? ph[2 * kt + 1][0] : 0u;
        A[3] = (kt < 3) ? ph[2 * kt + 1][1] : 0u;
#pragma unroll
        for (int nd = 0; nd < 4; nd++) {
            uint32_t baddr = smem_u32(&VT[nd * 8 + (lane >> 2)][cb + 16 * kt]);
            uint32_t bfr[2];
            lds32(bfr[0], baddr);
            lds32(bfr[1], baddr + 16);
            mma16816(oa[nd], A, bfr);
        }
    }

    // store (rows < 49 only)
    const float inv0 = r0ok ? 1.f / sum0 : 0.f;
    const float inv1 = r1ok ? 1.f / sum1 : 0.f;
    const size_t o0 = ((size_t)b * TT + r0) * DIM + h * HD;
    const size_t o1 = ((size_t)b * TT + r1) * DIM + h * HD;
#pragma unroll
    for (int nd = 0; nd < 4; nd++) {
        int dc = nd * 8 + cb;
        if (r0ok)
            *(__half2*)(c16 + o0 + dc) =
                __halves2half2(__float2half_rn(oa[nd][0] * inv0),
                               __float2half_rn(oa[nd][1] * inv0));
        if (r1ok)
            *(__half2*)(c16 + o1 + dc) =
                __halves2half2(__float2half_rn(oa[nd][2] * inv1),
                               __float2half_rn(oa[nd][3] * inv1));
    }
}

// ---------------------------------------------------------------------------
// Launch
// ---------------------------------------------------------------------------
extern "C" void kernel_launch(void* const* d_in, const int* in_sizes, int n_in,
                              void* d_out, int out_size) {
    const float* x          = (const float*)d_in[0];
    const float* qkv_w      = (const float*)d_in[1];
    const float* q_norm_w   = (const float*)d_in[2];
    const float* k_norm_w   = (const float*)d_in[3];
    const float* proj_w     = (const float*)d_in[4];
    const float* proj_b     = (const float*)d_in[5];
    const float* bias_table = (const float*)d_in[6];
    const int*   rel_index  = (const int*)d_in[7];
    float* out = (float*)d_out;

    float *biasb;
    __half *qkv16, *x16, *c16, *w16, *p16;
    cudaGetSymbolAddress((void**)&qkv16, g_qkv16);
    cudaGetSymbolAddress((void**)&biasb, g_biasg);
    cudaGetSymbolAddress((void**)&x16, g_x16);
    cudaGetSymbolAddress((void**)&c16, g_c16);
    cudaGetSymbolAddress((void**)&w16, g_w16);
    cudaGetSymbolAddress((void**)&p16, g_p16);

    // bias gather
    gather_bias_kernel<<<(HEADS * TT * TT + 255) / 256, 256>>>(bias_table, rel_index, biasb);

    // fp16 rounds
    {
        int n4 = (MROWS * DIM) / 4;
        round_kernel<<<(n4 + 255) / 256, 256>>>(x, x16, n4);
        int w4 = (NQKV * DIM) / 4;
        round_kernel<<<(w4 + 255) / 256, 256>>>(qkv_w, w16, w4);
        int p4 = (DIM * DIM) / 4;
        round_kernel<<<(p4 + 255) / 256, 256>>>(proj_w, p16, p4);
    }

    // qkv = x @ qkv_w^T  (HMMA fp16, fp16 output)
    {
        dim3 grid(NQKV / 128, MROWS / 128);
        gemm_hmma1<false, true><<<grid, 256>>>(x16, w16, nullptr, qkv16,
                                               MROWS, NQKV, DIM);
    }

    // fused windowed attention on tensor cores -> ctx (fp16)
    {
        dim3 grid(NWIN, HEADS);
        win_attn_mma<<<grid, 128>>>(qkv16, q_norm_w, k_norm_w, biasb, c16);
    }

    // out = ctx @ proj_w^T + proj_b  (fp32 output to d_out)
    {
        dim3 grid(DIM / 128, MROWS / 128);
        gemm_hmma1<true, false><<<grid, 256>>>(c16, p16, proj_b, out,
                                               MROWS, DIM, DIM);
    }
}

// round 17
// speedup vs baseline: 1.0820x; 1.0820x over previous
#include <cuda_runtime.h>
#include <cuda_fp16.h>
#include <cstdint>
#include <cstddef>

// Problem constants
#define NWIN   4096
#define TT     49
#define DIM    384
#define HEADS  12
#define HD     32
#define NQKV   1152
#define MROWS  (NWIN * TT)            // 200704
#define SCALE  0.17677669529663687f
#define EPS    1e-6f

#define AST    40                     // smem row stride in fp16 elems (80 B)
#define ASTAGE 10240                  // bytes per operand per stage (128*AST*2)
#define NSTAGE 3
#define GEMM_SMEM (2 * NSTAGE * ASTAGE)   // 61440 B dynamic

// ---------------------------------------------------------------------------
// Scratch (device globals; no allocations allowed)
// ---------------------------------------------------------------------------
__device__ __half g_qkv16[(size_t)MROWS * NQKV]; // 462 MB fp16 intermediate
__device__ __half g_x16[(size_t)MROWS * DIM];
__device__ __half g_c16[(size_t)MROWS * DIM];
__device__ __half g_w16[NQKV * DIM];             // qkv_w rounded to fp16
__device__ __half g_p16[DIM * DIM];              // proj_w rounded to fp16
__device__ float  g_biasg[HEADS * TT * TT];

// ---------------------------------------------------------------------------
// PTX helpers
// ---------------------------------------------------------------------------
__device__ __forceinline__ uint32_t smem_u32(const void* p) {
    uint32_t a;
    asm("{ .reg .u64 t; cvta.to.shared.u64 t, %1; cvt.u32.u64 %0, t; }"
        : "=r"(a) : "l"(p));
    return a;
}
__device__ __forceinline__ void cp_async16(uint32_t dst, const void* src) {
    asm volatile("cp.async.cg.shared.global [%0], [%1], 16;"
                 :: "r"(dst), "l"(src) : "memory");
}
__device__ __forceinline__ void ldsm4(uint32_t& r0, uint32_t& r1,
                                      uint32_t& r2, uint32_t& r3, uint32_t a) {
    asm volatile("ldmatrix.sync.aligned.m8n8.x4.shared.b16 {%0,%1,%2,%3}, [%4];"
                 : "=r"(r0), "=r"(r1), "=r"(r2), "=r"(r3) : "r"(a));
}
__device__ __forceinline__ void lds32(uint32_t& r, uint32_t a) {
    asm volatile("ld.shared.b32 %0, [%1];" : "=r"(r) : "r"(a));
}
__device__ __forceinline__ void mma16816(float* d, const uint32_t* a,
                                         const uint32_t* b) {
    asm volatile(
        "mma.sync.aligned.m16n8k16.row.col.f32.f16.f16.f32 "
        "{%0,%1,%2,%3}, {%4,%5,%6,%7}, {%8,%9}, {%0,%1,%2,%3};"
        : "+f"(d[0]), "+f"(d[1]), "+f"(d[2]), "+f"(d[3])
        : "r"(a[0]), "r"(a[1]), "r"(a[2]), "r"(a[3]), "r"(b[0]), "r"(b[1]));
}
// packed fp32x2 FMA (sm_100 family)
__device__ __forceinline__ uint64_t fma2(uint64_t a, uint64_t b, uint64_t c) {
    uint64_t d;
    asm("fma.rn.f32x2 %0, %1, %2, %3;" : "=l"(d) : "l"(a), "l"(b), "l"(c));
    return d;
}
__device__ __forceinline__ uint64_t pack2(float lo, float hi) {
    uint64_t d;
    asm("mov.b64 %0, {%1, %2};" : "=l"(d) : "f"(lo), "f"(hi));
    return d;
}
__device__ __forceinline__ float2 unpack2(uint64_t v) {
    float2 r;
    asm("mov.b64 {%0, %1}, %2;" : "=f"(r.x), "=f"(r.y) : "l"(v));
    return r;
}
__device__ __forceinline__ void lds_2x64(uint64_t& a, uint64_t& b, uint32_t addr) {
    asm volatile("ld.shared.v2.u64 {%0, %1}, [%2];" : "=l"(a), "=l"(b) : "r"(addr));
}

// ---------------------------------------------------------------------------
// HMMA GEMM: C[M,N] = A[M,K] @ B[N,K]^T (+bias). fp16 in, fp32 accum.
// BM=BN=128, BK=32, 8 warps (2x4), warp tile 64x32, m16n8k16.
// 3-stage cp.async pipeline, ONE __syncthreads per chunk (dynamic smem).
// ---------------------------------------------------------------------------
template<bool ADD_BIAS, bool OUT_HALF>
__global__ __launch_bounds__(256, 2)
void gemm_hmma1(const __half* __restrict__ A,
                const __half* __restrict__ B,
                const float* __restrict__ bias, void* __restrict__ Cv,
                int M, int N, int K) {
    extern __shared__ __half smb[];
    const uint32_t sA = smem_u32(smb);               // 3 stages x 10240 B
    const uint32_t sB = sA + NSTAGE * ASTAGE;        // 3 stages x 10240 B

    const int tid  = threadIdx.x;
    const int wid  = tid >> 5, lane = tid & 31;
    const int bm   = blockIdx.y * 128, bn = blockIdx.x * 128;
    const int wm   = (wid >> 2) * 64,  wn = (wid & 3) * 32;

    float acc[4][4][4];
#pragma unroll
    for (int i = 0; i < 4; i++)
#pragma unroll
        for (int j = 0; j < 4; j++)
#pragma unroll
            for (int r = 0; r < 4; r++) acc[i][j][r] = 0.f;

    const int nch = K >> 5;          // 12 for K=384

    const int lrow = tid >> 2;       // 0..63
    const int lhf  = tid & 3;        // 0..3 (x8 halves)

    const int m_l  = (lane & 7) + ((lane >> 3) & 1) * 8;
    const int kb_l = (lane >> 4) * 8;
    const int bn_l = lane >> 2;
    const int bk_l = (lane & 3) * 2;

#define PREFETCH(c, s)                                                          \
    do {                                                                        \
        int kc = (c) * 32;                                                      \
        _Pragma("unroll")                                                       \
        for (int j = 0; j < 2; j++) {                                           \
            int row = lrow + j * 64;                                            \
            uint32_t doff = (uint32_t)(s) * ASTAGE + (row * AST + lhf * 8) * 2; \
            cp_async16(sA + doff, A + (size_t)(bm + row) * K + kc + lhf * 8);   \
            cp_async16(sB + doff, B + (size_t)(bn + row) * K + kc + lhf * 8);   \
        }                                                                       \
        asm volatile("cp.async.commit_group;" ::: "memory");                    \
    } while (0)

    PREFETCH(0, 0);
    PREFETCH(1, 1);

    for (int c = 0; c < nch; c++) {
        // pending groups here: {c, c+1} (c+2 not yet committed)
        if (c + 1 < nch) {
            asm volatile("cp.async.wait_group 1;" ::: "memory");  // stage c ready
        } else {
            asm volatile("cp.async.wait_group 0;" ::: "memory");  // last stage
        }
        __syncthreads();   // all warps done with compute(c-1) -> stage (c+2)%3 free

        if (c + 2 < nch) PREFETCH(c + 2, (c + 2) % NSTAGE);

        const uint32_t aBase = sA + (uint32_t)(c % NSTAGE) * ASTAGE;
        const uint32_t bBase = sB + (uint32_t)(c % NSTAGE) * ASTAGE;
#pragma unroll
        for (int ks = 0; ks < 2; ks++) {
            const int k0 = ks * 16;
            uint32_t a[4][4], b[4][2];
#pragma unroll
            for (int mf = 0; mf < 4; mf++) {
                int m = wm + mf * 16 + m_l;
                ldsm4(a[mf][0], a[mf][1], a[mf][2], a[mf][3],
                      aBase + (m * AST + k0 + kb_l) * 2);
            }
#pragma unroll
            for (int nf = 0; nf < 4; nf++) {
                int n = wn + nf * 8 + bn_l;
                uint32_t addr = bBase + (n * AST + k0 + bk_l) * 2;
                lds32(b[nf][0], addr);
                lds32(b[nf][1], addr + 16);
            }
#pragma unroll
            for (int mf = 0; mf < 4; mf++)
#pragma unroll
                for (int nf = 0; nf < 4; nf++)
                    mma16816(acc[mf][nf], a[mf], b[nf]);
        }
    }
#undef PREFETCH

#pragma unroll
    for (int mf = 0; mf < 4; mf++) {
        int m0 = bm + wm + mf * 16 + (lane >> 2);
#pragma unroll
        for (int nf = 0; nf < 4; nf++) {
            int n0 = bn + wn + nf * 8 + (lane & 3) * 2;
            float bx = 0.f, by = 0.f;
            if (ADD_BIAS) { bx = bias[n0]; by = bias[n0 + 1]; }
            float2 v0 = make_float2(acc[mf][nf][0] + bx, acc[mf][nf][1] + by);
            float2 v1 = make_float2(acc[mf][nf][2] + bx, acc[mf][nf][3] + by);
            if (OUT_HALF) {
                __half* C = (__half*)Cv;
                *(__half2*)&C[(size_t)m0 * N + n0] =
                    __halves2half2(__float2half_rn(v0.x), __float2half_rn(v0.y));
                *(__half2*)&C[(size_t)(m0 + 8) * N + n0] =
                    __halves2half2(__float2half_rn(v1.x), __float2half_rn(v1.y));
            } else {
                float* C = (float*)Cv;
                *(float2*)&C[(size_t)m0 * N + n0]       = v0;
                *(float2*)&C[(size_t)(m0 + 8) * N + n0] = v1;
            }
        }
    }
}

// ---------------------------------------------------------------------------
// fp32 -> fp16 round
// ---------------------------------------------------------------------------
__global__ void round_kernel(const float* __restrict__ x,
                             __half* __restrict__ y, int n4) {
    int i = blockIdx.x * blockDim.x + threadIdx.x;
    if (i < n4) {
        float4 v = ((const float4*)x)[i];
        ((__half2*)y)[2 * i]     = __halves2half2(__float2half_rn(v.x), __float2half_rn(v.y));
        ((__half2*)y)[2 * i + 1] = __halves2half2(__float2half_rn(v.z), __float2half_rn(v.w));
    }
}

// ---------------------------------------------------------------------------
// bias gather
// ---------------------------------------------------------------------------
__global__ void gather_bias_kernel(const float* __restrict__ bt,
                                   const int* __restrict__ ri,
                                   float* __restrict__ ob) {
    int idx = blockIdx.x * blockDim.x + threadIdx.x;
    if (idx < HEADS * TT * TT) {
        int h = idx / (TT * TT);
        int p = idx - h * (TT * TT);
        ob[idx] = bt[ri[p] * HEADS + h];
    }
}

// ---------------------------------------------------------------------------
// Fused attention (R15-validated): one block per (window, head), 64 threads.
// qkv read as fp16, fp32 smem/compute, f32x2 packed inner loops, ctx fp16.
// ---------------------------------------------------------------------------
__global__ __launch_bounds__(64)
void win_attn_kernel(const __half* __restrict__ qkv,
                     const float* __restrict__ qn_w,
                     const float* __restrict__ kn_w,
                     const float* __restrict__ biasg,
                     __half* __restrict__ c16) {
    const int b = blockIdx.x;
    const int h = blockIdx.y;
    const int tid = threadIdx.x;

    __shared__ float qs[TT][36];
    __shared__ float ks[TT][36];
    __shared__ float vs[TT][36];
    __shared__ float S[TT][TT];
    __shared__ float nwq[HD], nwk[HD];

    if (tid < HD) { nwq[tid] = qn_w[tid]; nwk[tid] = kn_w[tid]; }

    const __half* base = qkv + (size_t)b * TT * NQKV + h * HD;
    for (int v4 = tid; v4 < TT * 4; v4 += 64) {
        int i = v4 >> 2, dv = v4 & 3;
        const __half* rp = base + (size_t)i * NQKV + dv * 8;
#pragma unroll
        for (int m = 0; m < 3; m++) {
            uint4 raw = *(const uint4*)(rp + m * DIM);
            float* dst = (m == 0 ? &qs[i][dv * 8] : m == 1 ? &ks[i][dv * 8]
                                                          : &vs[i][dv * 8]);
            __half2* hp = (__half2*)&raw;
#pragma unroll
            for (int p = 0; p < 4; p++) {
                float2 f = __half22float2(hp[p]);
                dst[2 * p] = f.x; dst[2 * p + 1] = f.y;
            }
        }
    }
    __syncthreads();

    uint64_t q2[16];
    if (tid < TT) {
        float qreg[HD];
        float ssq = 0.f, ssk = 0.f;
#pragma unroll
        for (int d = 0; d < HD; d++) {
            float q = qs[tid][d]; qreg[d] = q; ssq += q * q;
            float k = ks[tid][d]; ssk += k * k;
        }
        float rq = rsqrtf(ssq * (1.f / HD) + EPS) * SCALE;
        float rk = rsqrtf(ssk * (1.f / HD) + EPS);
#pragma unroll
        for (int d = 0; d < HD; d++) {
            qreg[d] = qreg[d] * rq * nwq[d];
            ks[tid][d] *= rk * nwk[d];
        }
#pragma unroll
        for (int p = 0; p < 16; p++)
            q2[p] = pack2(qreg[2 * p], qreg[2 * p + 1]);
    }
    __syncthreads();

    if (tid < TT) {
        const float* brow = biasg + ((size_t)h * TT + tid) * TT;
        const uint32_t ksb = smem_u32(ks);
        const uint32_t vsb = smem_u32(vs);

        float mx = -1e30f;
        for (int j = 0; j < TT; j++) {
            uint64_t acc0 = 0ull, acc1 = 0ull;
            uint32_t kr = ksb + (uint32_t)(j * 36 * 4);
#pragma unroll
            for (int dv = 0; dv < 8; dv++) {
                uint64_t ka, kb;
                lds_2x64(ka, kb, kr + dv * 16);
                acc0 = fma2(q2[2 * dv],     ka, acc0);
                acc1 = fma2(q2[2 * dv + 1], kb, acc1);
            }
            float2 a0 = unpack2(acc0), a1 = unpack2(acc1);
            float s = (a0.x + a0.y) + (a1.x + a1.y) + brow[j];
            S[tid][j] = s;
            mx = fmaxf(mx, s);
        }
        float sum = 0.f;
        for (int j = 0; j < TT; j++) {
            float e = __expf(S[tid][j] - mx);
            S[tid][j] = e;
            sum += e;
        }
        float inv = 1.f / sum;

        uint64_t o2[16];
#pragma unroll
        for (int p = 0; p < 16; p++) o2[p] = 0ull;
        for (int j = 0; j < TT; j++) {
            float p = S[tid][j];
            uint64_t pp = pack2(p, p);
            uint32_t vr = vsb + (uint32_t)(j * 36 * 4);
#pragma unroll
            for (int dv = 0; dv < 8; dv++) {
                uint64_t va, vb;
                lds_2x64(va, vb, vr + dv * 16);
                o2[2 * dv]     = fma2(pp, va, o2[2 * dv]);
                o2[2 * dv + 1] = fma2(pp, vb, o2[2 * dv + 1]);
            }
        }

        size_t co = ((size_t)b * TT + tid) * DIM + h * HD;
#pragma unroll
        for (int p = 0; p < 16; p++) {
            float2 o = unpack2(o2[p]);
            *(__half2*)(c16 + co + p * 2) =
                __halves2half2(__float2half_rn(o.x * inv),
                               __float2half_rn(o.y * inv));
        }
    }
}

// ---------------------------------------------------------------------------
// Launch
// ---------------------------------------------------------------------------
extern "C" void kernel_launch(void* const* d_in, const int* in_sizes, int n_in,
                              void* d_out, int out_size) {
    const float* x          = (const float*)d_in[0];
    const float* qkv_w      = (const float*)d_in[1];
    const float* q_norm_w   = (const float*)d_in[2];
    const float* k_norm_w   = (const float*)d_in[3];
    const float* proj_w     = (const float*)d_in[4];
    const float* proj_b     = (const float*)d_in[5];
    const float* bias_table = (const float*)d_in[6];
    const int*   rel_index  = (const int*)d_in[7];
    float* out = (float*)d_out;

    float *biasb;
    __half *qkv16, *x16, *c16, *w16, *p16;
    cudaGetSymbolAddress((void**)&qkv16, g_qkv16);
    cudaGetSymbolAddress((void**)&biasb, g_biasg);
    cudaGetSymbolAddress((void**)&x16, g_x16);
    cudaGetSymbolAddress((void**)&c16, g_c16);
    cudaGetSymbolAddress((void**)&w16, g_w16);
    cudaGetSymbolAddress((void**)&p16, g_p16);

    cudaFuncSetAttribute(gemm_hmma1<false, true>,
                         cudaFuncAttributeMaxDynamicSharedMemorySize, GEMM_SMEM);
    cudaFuncSetAttribute(gemm_hmma1<true, false>,
                         cudaFuncAttributeMaxDynamicSharedMemorySize, GEMM_SMEM);

    // bias gather
    gather_bias_kernel<<<(HEADS * TT * TT + 255) / 256, 256>>>(bias_table, rel_index, biasb);

    // fp16 rounds
    {
        int n4 = (MROWS * DIM) / 4;
        round_kernel<<<(n4 + 255) / 256, 256>>>(x, x16, n4);
        int w4 = (NQKV * DIM) / 4;
        round_kernel<<<(w4 + 255) / 256, 256>>>(qkv_w, w16, w4);
        int p4 = (DIM * DIM) / 4;
        round_kernel<<<(p4 + 255) / 256, 256>>>(proj_w, p16, p4);
    }

    // qkv = x @ qkv_w^T  (HMMA fp16, fp16 output)
    {
        dim3 grid(NQKV / 128, MROWS / 128);
        gemm_hmma1<false, true><<<grid, 256, GEMM_SMEM>>>(x16, w16, nullptr, qkv16,
                                                          MROWS, NQKV, DIM);
    }

    // fused windowed attention -> ctx (fp16)
    {
        dim3 grid(NWIN, HEADS);
        win_attn_kernel<<<grid, 64>>>(qkv16, q_norm_w, k_norm_w, biasb, c16);
    }

    // out = ctx @ proj_w^T + proj_b  (fp32 output to d_out)
    {
        dim3 grid(DIM / 128, MROWS / 128);
        gemm_hmma1<true, false><<<grid, 256, GEMM_SMEM>>>(c16, p16, proj_b, out,
                                                          MROWS, DIM, DIM);
    }
}